// round 14
// baseline (speedup 1.0000x reference)
#include <cuda_runtime.h>
#include <cstdint>

#define N_TOK 131072
#define KC 256
#define DD 128
#define OFF_IDX  16777216
#define OFF_COMM 16908288
#define OFF_CBL  16908289
#define OFF_NCB  16908290
#define OFF_NC   16941058
#define OFF_NW   16941314

__device__ int   g_idx[N_TOK];
__device__ float g_ebp[(size_t)128 * KC * DD];   // per-b enc_batch partials
__device__ float g_esp[128 * KC];                // per-b enc_sum partials
__device__ float g_lp[2048];                     // per-block loss partials
__device__ float g_cbT[DD * KC];                 // codebook transposed [c][k]
__device__ float g_c2[KC];
__device__ float g_norm[KC];

__device__ __forceinline__ void fma2(unsigned long long& d, unsigned long long a, unsigned long long b) {
    asm("fma.rn.f32x2 %0,%1,%2,%0;" : "+l"(d) : "l"(a), "l"(b));
}
__device__ __forceinline__ void upk(unsigned long long v, float& a, float& b) {
    asm("mov.b64 {%0,%1},%2;" : "=f"(a), "=f"(b) : "l"(v));
}
__device__ __forceinline__ unsigned long long pk2(float f) {
    unsigned long long r; asm("mov.b64 %0,{%1,%1};" : "=l"(r) : "f"(f)); return r;
}

// ---- kernel 0: transpose codebook + per-code squared norm (proven) ----
__global__ void prep_kernel(const float* __restrict__ cb) {
    int k = blockIdx.x, c = threadIdx.x;
    __shared__ float s[DD];
    float v = cb[k * DD + c];
    g_cbT[c * KC + k] = v; s[c] = v;
    __syncthreads();
    if (c == 0) {
        float acc = 0.f;
        for (int i = 0; i < DD; i++) acc = __fadd_rn(acc, __fmul_rn(s[i], s[i]));
        g_c2[k] = acc;
    }
}

// ---- kernel 1: fp32 FFMA2 distances + argmin + quantized + idx + loss ----
// grid 2048 (64-token tiles), block 256. smem 166400 B.
// smem: cbs[128][256] | zsc[128][64] | c2s[256] | z2s[64] | red[256] | idxs[64]
__global__ void __launch_bounds__(256, 1)
assign_kernel(const float* __restrict__ z, float* __restrict__ out) {
    extern __shared__ float sm[];
    float* cbs = sm;                 // 32768
    float* zsc = sm + 32768;         // 8192  [c][t] stride 64
    float* c2s = sm + 40960;         // 256
    float* z2s = c2s + 256;          // 64
    float* red = z2s + 64;           // 256
    int*  idxs = (int*)(red + 256);  // 64

    const int tid = threadIdx.x, T = blockIdx.x, b = T >> 4, h2 = T & 15;
    const float* zb = z + (size_t)b * 131072 + h2 * 64;

    { const float4* s4 = (const float4*)g_cbT; float4* d4 = (float4*)cbs;
      #pragma unroll
      for (int i = 0; i < 32; i++) d4[tid + i * 256] = s4[tid + i * 256]; }
    c2s[tid] = g_c2[tid];

    #pragma unroll
    for (int it = 0; it < 8; it++) {
        int c = it * 16 + (tid >> 4), p = tid & 15;
        float4 v = *(const float4*)(zb + (size_t)c * 1024 + p * 4);
        *(float4*)(zsc + c * 64 + p * 4) = v;
    }
    __syncthreads();

    if (tid < 64) {   // z2: sequential square-then-add (proven rounding order)
        float s = 0.f;
        for (int c = 0; c < DD; c++) {
            float zv = zsc[c * 64 + tid];
            s = __fadd_rn(s, __fmul_rn(zv, zv));
        }
        z2s[tid] = s;
    }
    __syncthreads();

    // warp w: tokens [8w,8w+8); lane l: codes {4l..4l+3, 128+4l..128+4l+3}
    const int w = tid >> 5, l = tid & 31, t0 = w * 8;
    unsigned long long A0[8], A1[8], B0[8], B1[8];
    #pragma unroll
    for (int t = 0; t < 8; t++) { A0[t] = 0; A1[t] = 0; B0[t] = 0; B1[t] = 0; }
    const float* cbp = cbs + 4 * l;
    #pragma unroll 4
    for (int c = 0; c < 128; c++) {
        ulonglong2 ca  = *(const ulonglong2*)(cbp + (c << 8));
        ulonglong2 cb2 = *(const ulonglong2*)(cbp + (c << 8) + 128);
        float4 zlo = *(const float4*)(zsc + (c << 6) + t0);      // broadcast
        float4 zhi = *(const float4*)(zsc + (c << 6) + t0 + 4);  // broadcast
        unsigned long long zz;
        zz = pk2(zlo.x);
        fma2(A0[0], zz, ca.x); fma2(A1[0], zz, ca.y); fma2(B0[0], zz, cb2.x); fma2(B1[0], zz, cb2.y);
        zz = pk2(zlo.y);
        fma2(A0[1], zz, ca.x); fma2(A1[1], zz, ca.y); fma2(B0[1], zz, cb2.x); fma2(B1[1], zz, cb2.y);
        zz = pk2(zlo.z);
        fma2(A0[2], zz, ca.x); fma2(A1[2], zz, ca.y); fma2(B0[2], zz, cb2.x); fma2(B1[2], zz, cb2.y);
        zz = pk2(zlo.w);
        fma2(A0[3], zz, ca.x); fma2(A1[3], zz, ca.y); fma2(B0[3], zz, cb2.x); fma2(B1[3], zz, cb2.y);
        zz = pk2(zhi.x);
        fma2(A0[4], zz, ca.x); fma2(A1[4], zz, ca.y); fma2(B0[4], zz, cb2.x); fma2(B1[4], zz, cb2.y);
        zz = pk2(zhi.y);
        fma2(A0[5], zz, ca.x); fma2(A1[5], zz, ca.y); fma2(B0[5], zz, cb2.x); fma2(B1[5], zz, cb2.y);
        zz = pk2(zhi.z);
        fma2(A0[6], zz, ca.x); fma2(A1[6], zz, ca.y); fma2(B0[6], zz, cb2.x); fma2(B1[6], zz, cb2.y);
        zz = pk2(zhi.w);
        fma2(A0[7], zz, ca.x); fma2(A1[7], zz, ca.y); fma2(B0[7], zz, cb2.x); fma2(B1[7], zz, cb2.y);
    }

    // d = (z2 - 2*zc) + c2, proven op order; strict < => first-index ties
    #pragma unroll
    for (int t = 0; t < 8; t++) {
        float z2v = z2s[t0 + t], lo, hi, d, best; int bi;
        upk(A0[t], lo, hi);
        best = __fadd_rn(__fadd_rn(z2v, -2.f * lo), c2s[4 * l]);      bi = 4 * l;
        d = __fadd_rn(__fadd_rn(z2v, -2.f * hi), c2s[4 * l + 1]);     if (d < best) { best = d; bi = 4 * l + 1; }
        upk(A1[t], lo, hi);
        d = __fadd_rn(__fadd_rn(z2v, -2.f * lo), c2s[4 * l + 2]);     if (d < best) { best = d; bi = 4 * l + 2; }
        d = __fadd_rn(__fadd_rn(z2v, -2.f * hi), c2s[4 * l + 3]);     if (d < best) { best = d; bi = 4 * l + 3; }
        upk(B0[t], lo, hi);
        d = __fadd_rn(__fadd_rn(z2v, -2.f * lo), c2s[128 + 4 * l]);   if (d < best) { best = d; bi = 128 + 4 * l; }
        d = __fadd_rn(__fadd_rn(z2v, -2.f * hi), c2s[129 + 4 * l]);   if (d < best) { best = d; bi = 129 + 4 * l; }
        upk(B1[t], lo, hi);
        d = __fadd_rn(__fadd_rn(z2v, -2.f * lo), c2s[130 + 4 * l]);   if (d < best) { best = d; bi = 130 + 4 * l; }
        d = __fadd_rn(__fadd_rn(z2v, -2.f * hi), c2s[131 + 4 * l]);   if (d < best) { best = d; bi = 131 + 4 * l; }
        #pragma unroll
        for (int off = 16; off; off >>= 1) {
            float ob = __shfl_down_sync(0xffffffffu, best, off);
            int   oi = __shfl_down_sync(0xffffffffu, bi, off);
            if (ob < best || (ob == best && oi < bi)) { best = ob; bi = oi; }
        }
        if (l == 0) idxs[t0 + t] = bi;
    }
    __syncthreads();

    if (tid < 64) {
        int n = T * 64 + tid, k = idxs[tid];
        g_idx[n] = k; out[OFF_IDX + n] = (float)k;
    }
    float ls = 0.f;
    { int q = tid >> 6, tl = tid & 63, k = idxs[tl];
      float* ob = out + (size_t)b * 131072 + h2 * 64 + tl;
      #pragma unroll
      for (int i = 0; i < 32; i++) {
          int c = i * 4 + q;
          float qv = cbs[c * 256 + k], zv = zsc[c * 64 + tl];
          float df = __fsub_rn(zv, qv);
          ls = __fmaf_rn(df, df, ls);
          ob[(size_t)c * 1024] = __fadd_rn(zv, __fsub_rn(qv, zv));  // straight-through value
      } }
    red[tid] = ls; __syncthreads();
    #pragma unroll
    for (int o = 128; o; o >>= 1) { if (tid < o) red[tid] += red[tid + o]; __syncthreads(); }
    if (tid == 0) g_lp[T] = red[0];
}

// ---- kernel 2: segment-sum partials via smem atomics ----
// grid 128 (one b, 1024 tokens), block 128 (thread = channel c; single writer
// per acc column -> deterministic; counts are exact +1.0 adds -> order-free).
// smem: acc[256][128]=32768 f | cnt[256] | sidx[1024] i  -> 136192 B
__global__ void __launch_bounds__(128, 1)
aggregate_kernel(const float* __restrict__ z) {
    extern __shared__ float sm[];
    float* acc  = sm;                       // 32768 floats
    float* cnt  = sm + 32768;               // 256
    int*   sidx = (int*)(sm + 33024);       // 1024
    const int tid = threadIdx.x, b = blockIdx.x;

    { float4 zf = make_float4(0.f, 0.f, 0.f, 0.f);
      float4* a4 = (float4*)acc;
      #pragma unroll
      for (int i = tid; i < 8192; i += 128) a4[i] = zf; }
    cnt[tid] = 0.f; cnt[tid + 128] = 0.f;
    for (int i = tid; i < 1024; i += 128) sidx[i] = g_idx[b * 1024 + i];
    __syncthreads();

    const float* zc = z + (size_t)b * 131072 + (size_t)tid * 1024;
    float* ac = acc + tid;
    #pragma unroll 4
    for (int t = 0; t < 1024; t += 4) {
        float4 v = *(const float4*)(zc + t);
        atomicAdd(ac + sidx[t]     * 128, v.x);
        atomicAdd(ac + sidx[t + 1] * 128, v.y);
        atomicAdd(ac + sidx[t + 2] * 128, v.z);
        atomicAdd(ac + sidx[t + 3] * 128, v.w);
    }
    #pragma unroll
    for (int j = 0; j < 8; j++) atomicAdd(cnt + sidx[tid * 8 + j], 1.0f);
    __syncthreads();

    { float4* a4 = (float4*)acc; float4* o4 = (float4*)(g_ebp + (size_t)b * 32768);
      for (int i = tid; i < 8192; i += 128) o4[i] = a4[i]; }
    g_esp[b * KC + tid] = cnt[tid];
    g_esp[b * KC + tid + 128] = cnt[tid + 128];
}

// ---- kernel 3: reduce partials -> new_weight / new_count ----
__global__ void fin1_kernel(const float* __restrict__ emaw, const float* __restrict__ emac,
                            float* __restrict__ out) {
    __shared__ float part[256];
    __shared__ float red[128];
    int k = blockIdx.x, tid = threadIdx.x;
    int c = tid & 127, h = tid >> 7;
    float wv = 0.f;
    #pragma unroll 16
    for (int b = h * 64; b < h * 64 + 64; b++) wv += g_ebp[(size_t)b * 32768 + k * DD + c];
    part[tid] = wv;
    if (h == 0) red[c] = g_esp[c * KC + k];
    __syncthreads();
    if (h == 0)
        out[OFF_NW + k * DD + c] = 0.99f * emaw[k * DD + c] + 0.01f * (part[c] + part[c + 128]);
    #pragma unroll
    for (int o = 64; o; o >>= 1) { if (tid < o) red[tid] += red[tid + o]; __syncthreads(); }
    if (tid == 0) out[OFF_NC + k] = 0.99f * emac[k] + 0.01f * red[0];
}

// ---- kernel 4: n, normalized_count, losses ----
__global__ void fin2_kernel(float* __restrict__ out) {
    __shared__ float red[256];
    int tid = threadIdx.x;
    float v = out[OFF_NC + tid];
    red[tid] = v; __syncthreads();
    #pragma unroll
    for (int o = 128; o; o >>= 1) { if (tid < o) red[tid] += red[tid + o]; __syncthreads(); }
    float n = red[0];
    g_norm[tid] = __fmul_rn(__fdiv_rn(__fadd_rn(v, 1e-5f), __fadd_rn(n, 0.00256f)), n);
    float ls = 0.f;
    for (int i = 0; i < 8; i++) ls += g_lp[tid * 8 + i];
    red[tid] = ls; __syncthreads();
    #pragma unroll
    for (int o = 128; o; o >>= 1) { if (tid < o) red[tid] += red[tid + o]; __syncthreads(); }
    if (tid == 0) {
        float m = red[0] / 16777216.0f;
        out[OFF_COMM] = 0.25f * m;
        out[OFF_CBL]  = m;
    }
}

// ---- kernel 5: new_codebook ----
__global__ void fin3_kernel(float* __restrict__ out) {
    int i = blockIdx.x * 256 + threadIdx.x;
    out[OFF_NCB + i] = __fdiv_rn(out[OFF_NW + i], g_norm[i >> 7]);
}

extern "C" void kernel_launch(void* const* d_in, const int* in_sizes, int n_in,
                              void* d_out, int out_size) {
    const float* z    = (const float*)d_in[0];
    const float* cb   = (const float*)d_in[1];
    const float* emac = (const float*)d_in[2];
    const float* emaw = (const float*)d_in[3];
    float* out = (float*)d_out;

    cudaFuncSetAttribute(assign_kernel,    cudaFuncAttributeMaxDynamicSharedMemorySize, 166400);
    cudaFuncSetAttribute(aggregate_kernel, cudaFuncAttributeMaxDynamicSharedMemorySize, 136192);

    prep_kernel<<<256, 128>>>(cb);
    assign_kernel<<<2048, 256, 166400>>>(z, out);
    aggregate_kernel<<<128, 128, 136192>>>(z);
    fin1_kernel<<<256, 256>>>(emaw, emac, out);
    fin2_kernel<<<1, 256>>>(out);
    fin3_kernel<<<128, 256>>>(out);
}